// round 4
// baseline (speedup 1.0000x reference)
#include <cuda_runtime.h>
#include <cuda_bf16.h>

#define NUM_CLASSES 601
#define OUT_DIM 27
#define PAD_DIM 28          // pad rows to 28 floats (112 B) for aligned float4 loads
#define TILE_ROWS 256
#define TILE_FLOATS (TILE_ROWS * OUT_DIM)   // 6912 floats = 27648 B
#define TILE_VEC4 (TILE_FLOATS / 4)         // 1728 float4

// Precomputed softmax table: 601 rows x 28 floats (last col = padding 0)
__device__ float g_table[NUM_CLASSES * PAD_DIM];

// ---------------------------------------------------------------------------
// Kernel A: build softmax table. One warp per class row.
// softmax with no max-subtraction, exactly matching the reference (exp / sum).
// ---------------------------------------------------------------------------
__global__ void softmax_table_kernel(const float* __restrict__ W) {
    int r = blockIdx.x;          // 0..600
    int c = threadIdx.x;         // 0..31
    float e = 0.0f;
    if (c < OUT_DIM) {
        e = expf(W[r * OUT_DIM + c]);
    }
    // warp-reduce sum (lanes >= 27 contribute 0)
    float s = e;
    #pragma unroll
    for (int off = 16; off > 0; off >>= 1)
        s += __shfl_xor_sync(0xffffffffu, s, off);
    if (c < PAD_DIM) {
        g_table[r * PAD_DIM + c] = (c < OUT_DIM) ? (e / s) : 0.0f;
    }
}

// ---------------------------------------------------------------------------
// Kernel B: gather + coalesced writeout.
// Each block handles TILE_ROWS=256 output rows:
//   1. each thread loads its row index (coalesced)
//   2. fetches its 27-float table row via 7x LDG.128 (table is L1-resident, 65KB)
//   3. stores packed into smem staging (27t+c is conflict-free mod 32)
//   4. block writes the contiguous 27648B tile with coalesced STG.128
// ---------------------------------------------------------------------------
__global__ void __launch_bounds__(TILE_ROWS) gather_kernel(
    const int* __restrict__ idx, float* __restrict__ out, int batch)
{
    __shared__ __align__(16) float stage[TILE_FLOATS];
    const int t = threadIdx.x;
    const long long row0 = (long long)blockIdx.x * TILE_ROWS;
    const long long myrow = row0 + t;

    if (myrow < batch) {
        int r = idx[myrow];
        const float4* rowp = reinterpret_cast<const float4*>(g_table + r * PAD_DIM);
        float4 v[7];
        #pragma unroll
        for (int i = 0; i < 7; i++) v[i] = __ldg(rowp + i);

        float* s = stage + t * OUT_DIM;
        #pragma unroll
        for (int i = 0; i < 7; i++) {
            s[i * 4 + 0] = v[i].x;
            if (i * 4 + 1 < OUT_DIM) s[i * 4 + 1] = v[i].y;
            if (i * 4 + 2 < OUT_DIM) s[i * 4 + 2] = v[i].z;
            if (i * 4 + 3 < OUT_DIM) s[i * 4 + 3] = v[i].w;
        }
    }
    __syncthreads();

    const long long rows_here = batch - row0;   // >= 1
    if (rows_here >= TILE_ROWS) {
        // full tile: vectorized coalesced writeout
        float4* outp = reinterpret_cast<float4*>(out + row0 * OUT_DIM);
        const float4* sp = reinterpret_cast<const float4*>(stage);
        #pragma unroll
        for (int k = 0; k < 7; k++) {
            int j = t + k * TILE_ROWS;
            if (j < TILE_VEC4) outp[j] = sp[j];
        }
    } else {
        // tail tile: scalar coalesced writeout
        long long nf = rows_here * OUT_DIM;
        float* outp = out + row0 * OUT_DIM;
        for (long long j = t; j < nf; j += TILE_ROWS) outp[j] = stage[j];
    }
}

extern "C" void kernel_launch(void* const* d_in, const int* in_sizes, int n_in,
                              void* d_out, int out_size) {
    const int* idx;
    const float* W;
    int batch;
    if (in_sizes[0] == NUM_CLASSES * OUT_DIM) {
        W = (const float*)d_in[0];
        idx = (const int*)d_in[1];
        batch = in_sizes[1];
    } else {
        idx = (const int*)d_in[0];
        W = (const float*)d_in[1];
        batch = in_sizes[0];
    }

    softmax_table_kernel<<<NUM_CLASSES, 32>>>(W);

    int nblocks = (int)(((long long)batch + TILE_ROWS - 1) / TILE_ROWS);
    gather_kernel<<<nblocks, TILE_ROWS>>>(idx, (float*)d_out, batch);
}